// round 1
// baseline (speedup 1.0000x reference)
#include <cuda_runtime.h>
#include <cstdint>

// exp(X) for batched 32x32 symmetric fp32 matrices via scaling-and-squaring
// with degree-8 Paterson-Stockmeyer Taylor. One warp per matrix.
// Lane j owns column j of every matmul result in registers (as 16 x f32x2).

#define STRIDE 36                 // floats per smem row (conflict-free + 16B aligned)
#define MATF   (STRIDE * 32)      // 1152 floats per matrix buffer
#define WARPS_PER_CTA 2

__device__ __forceinline__ unsigned long long pk2(float lo, float hi) {
    unsigned long long r;
    asm("mov.b64 %0, {%1, %2};" : "=l"(r) : "f"(lo), "f"(hi));
    return r;
}
__device__ __forceinline__ void upk2(float& lo, float& hi, unsigned long long v) {
    asm("mov.b64 {%0, %1}, %2;" : "=f"(lo), "=f"(hi) : "l"(v));
}
__device__ __forceinline__ void fma2(unsigned long long& d, unsigned long long a,
                                     unsigned long long b) {
    asm("fma.rn.f32x2 %0, %1, %2, %0;" : "+l"(d) : "l"(a), "l"(b));
}

// C(:,j) = A * B(:,j); A rows broadcast from smem, B column per-lane from smem.
// acc[p] holds rows (2p, 2p+1) of column j, packed f32x2.
__device__ __forceinline__ void mm32(uint32_t aB, uint32_t bB, int j,
                                     unsigned long long acc[16]) {
    float rB[32];
#pragma unroll
    for (int k = 0; k < 32; ++k) {
        asm volatile("ld.shared.f32 %0, [%1];"
                     : "=f"(rB[k]) : "r"(bB + (uint32_t)((k * STRIDE + j) * 4)));
    }
#pragma unroll
    for (int p = 0; p < 16; ++p) acc[p] = 0ULL;
#pragma unroll
    for (int k = 0; k < 32; ++k) {
        unsigned long long bb = pk2(rB[k], rB[k]);
        uint32_t ra = aB + (uint32_t)(k * STRIDE * 4);
#pragma unroll
        for (int q = 0; q < 8; ++q) {
            unsigned long long a0, a1;
            asm volatile("ld.shared.v2.u64 {%0, %1}, [%2];"
                         : "=l"(a0), "=l"(a1) : "r"(ra + (uint32_t)(q * 16)));
            fma2(acc[2 * q],     a0, bb);
            fma2(acc[2 * q + 1], a1, bb);
        }
    }
}

__global__ void __launch_bounds__(WARPS_PER_CTA * 32)
ExpEig_52553219834314_kernel(const float* __restrict__ in,
                             float* __restrict__ out, int B) {
    __shared__ __align__(16) float smem[WARPS_PER_CTA][4 * MATF];

    const int w = threadIdx.x >> 5;
    const int j = threadIdx.x & 31;
    const int b = blockIdx.x * WARPS_PER_CTA + w;
    if (b >= B) return;

    float* bufA = smem[w];            // X -> Xs -> P -> squarings
    float* bufB = bufA + MATF;        // X2s
    float* bufC = bufB + MATF;        // Z = Xs^3
    float* bufD = bufC + MATF;        // B2 -> (B2*Z + B1)
    const uint32_t aAddr = (uint32_t)__cvta_generic_to_shared(bufA);
    const uint32_t bAddr = (uint32_t)__cvta_generic_to_shared(bufB);
    const uint32_t cAddr = (uint32_t)__cvta_generic_to_shared(bufC);
    const uint32_t dAddr = (uint32_t)__cvta_generic_to_shared(bufD);

    // Load X (row-major, symmetric). Coalesced: lane j loads column j elements.
    const float* src = in + (size_t)b * 1024;
#pragma unroll
    for (int i = 0; i < 32; ++i) bufA[i * STRIDE + j] = src[i * 32 + j];
    __syncwarp();

    unsigned long long acc[16];
    float c[32];
    int total = 4;  // updated after stage 0 to 4 + k

    for (int s = 0; s < total; ++s) {
        uint32_t aB, bB;
        if (s == 0)      { aB = aAddr; bB = aAddr; }   // X2 = X * X
        else if (s == 1) { aB = aAddr; bB = bAddr; }   // Z  = Xs * X2s
        else if (s == 2) { aB = dAddr; bB = cAddr; }   // M1 = B2 * Z
        else if (s == 3) { aB = dAddr; bB = cAddr; }   // M2 = (M1+B1) * Z
        else             { aB = aAddr; bB = aAddr; }   // P  = P * P

        mm32(aB, bB, j, acc);
#pragma unroll
        for (int p = 0; p < 16; ++p) upk2(c[2 * p], c[2 * p + 1], acc[p]);
        __syncwarp();  // all smem reads of this stage complete before rewrites

        if (s == 0) {
            // Spectral bound from X2: ||X||_2 <= sqrt(min(||X2||_1, ||X2||_F)).
            float rs = 0.f, fb = 0.f;
#pragma unroll
            for (int i = 0; i < 32; ++i) { rs += fabsf(c[i]); fb += c[i] * c[i]; }
#pragma unroll
            for (int off = 16; off > 0; off >>= 1) {
                rs = fmaxf(rs, __shfl_xor_sync(0xffffffffu, rs, off));
                fb += __shfl_xor_sync(0xffffffffu, fb, off);
            }
            float bound = sqrtf(fminf(rs, sqrtf(fb)));
            int e = 0;
            (void)frexpf(bound, &e);          // bound <= 2^e
            int kk = e < 0 ? 0 : (e > 24 ? 24 : e);
            total = 4 + kk;
            float s1 = exp2f(-(float)kk);
            float s2 = s1 * s1;
#pragma unroll
            for (int i = 0; i < 32; ++i) {
                bufA[i * STRIDE + j] *= s1;          // Xs
                bufB[i * STRIDE + j] = c[i] * s2;    // X2s
            }
        } else if (s == 1) {
            // store Z; build B2 = I/720 + Xs/5040 + X2s/40320
#pragma unroll
            for (int i = 0; i < 32; ++i) {
                bufC[i * STRIDE + j] = c[i];
                float d = (i == j) ? (1.f / 720.f) : 0.f;
                d += bufA[i * STRIDE + j] * (1.f / 5040.f);
                d += bufB[i * STRIDE + j] * (1.f / 40320.f);
                bufD[i * STRIDE + j] = d;
            }
        } else if (s == 2) {
            // M1 += B1 = I/6 + Xs/24 + X2s/120  -> bufD
#pragma unroll
            for (int i = 0; i < 32; ++i) {
                float v = c[i];
                if (i == j) v += (1.f / 6.f);
                v += bufA[i * STRIDE + j] * (1.f / 24.f);
                v += bufB[i * STRIDE + j] * (1.f / 120.f);
                c[i] = v;
                bufD[i * STRIDE + j] = v;
            }
        } else if (s == 3) {
            // P = M2 + B0 = M2 + I + Xs + X2s/2  -> bufA
#pragma unroll
            for (int i = 0; i < 32; ++i) {
                float v = c[i];
                if (i == j) v += 1.f;
                v += bufA[i * STRIDE + j];
                v += bufB[i * STRIDE + j] * 0.5f;
                c[i] = v;
                bufA[i * STRIDE + j] = v;
            }
        } else {
            // squaring: write P back in place (reads already fenced above)
#pragma unroll
            for (int i = 0; i < 32; ++i) bufA[i * STRIDE + j] = c[i];
        }
        __syncwarp();
    }

    // c[] holds the final column j. Coalesced store.
    float* dst = out + (size_t)b * 1024;
#pragma unroll
    for (int i = 0; i < 32; ++i) dst[i * 32 + j] = c[i];
}

extern "C" void kernel_launch(void* const* d_in, const int* in_sizes, int n_in,
                              void* d_out, int out_size) {
    (void)n_in; (void)out_size;
    const float* x = (const float*)d_in[0];
    float* out = (float*)d_out;
    const int B = in_sizes[0] / 1024;  // 32x32 per matrix
    const int ctas = (B + WARPS_PER_CTA - 1) / WARPS_PER_CTA;
    ExpEig_52553219834314_kernel<<<ctas, WARPS_PER_CTA * 32>>>(x, out, B);
}

// round 2
// speedup vs baseline: 1.3251x; 1.3251x over previous
#include <cuda_runtime.h>
#include <cstdint>

// exp(X) for batched 32x32 symmetric fp32 via scaling-and-squaring, degree-8
// Paterson-Stockmeyer Taylor. TWO matrices per warp: half-warp h owns matrix h,
// lane (h,jj) owns columns jj and jj+16 of its matrix. A-operand rows come from
// smem (two distinct 16B rows per LDS.128, bank-disjoint via 16-word offset);
// B-operand columns live entirely in registers (previous stage's result).

#define STRIDE 36               // floats per smem row (conflict-free, 16B aligned)
#define MATF   1152             // floats per matrix buffer (32*36)
#define MOFF   1168             // matrix-1 offset inside a buffer: +16-word bank shift
#define BUFF   2320             // floats per buffer (2 matrices)

typedef unsigned long long u64;

__device__ __forceinline__ u64 pk2(float lo, float hi) {
    u64 r; asm("mov.b64 %0, {%1, %2};" : "=l"(r) : "f"(lo), "f"(hi)); return r;
}
__device__ __forceinline__ void upk2(float& lo, float& hi, u64 v) {
    asm("mov.b64 {%0, %1}, %2;" : "=f"(lo), "=f"(hi) : "l"(v));
}
__device__ __forceinline__ void fma2(u64& d, u64 a, u64 b) {
    asm("fma.rn.f32x2 %0, %1, %2, %0;" : "+l"(d) : "l"(a), "l"(b));
}

// C(:,c0|c1) = A * b, A rows from smem (my matrix), b columns in registers.
__device__ __forceinline__ void mm2(uint32_t aBase, const float* bc0, const float* bc1,
                                    u64 acc0[16], u64 acc1[16]) {
#pragma unroll
    for (int p = 0; p < 16; ++p) { acc0[p] = 0ULL; acc1[p] = 0ULL; }
#pragma unroll
    for (int k = 0; k < 32; ++k) {
        u64 bb0 = pk2(bc0[k], bc0[k]);
        u64 bb1 = pk2(bc1[k], bc1[k]);
        uint32_t ra = aBase + (uint32_t)(k * STRIDE * 4);
#pragma unroll
        for (int q = 0; q < 8; ++q) {
            u64 a0, a1;
            asm volatile("ld.shared.v2.u64 {%0, %1}, [%2];"
                         : "=l"(a0), "=l"(a1) : "r"(ra + (uint32_t)(q * 16)));
            fma2(acc0[2 * q],     a0, bb0);
            fma2(acc0[2 * q + 1], a1, bb0);
            fma2(acc1[2 * q],     a0, bb1);
            fma2(acc1[2 * q + 1], a1, bb1);
        }
    }
}

__global__ void __launch_bounds__(32)
ExpEig_52553219834314_kernel(const float* __restrict__ in,
                             float* __restrict__ out, int B) {
    __shared__ __align__(16) float smem[3 * BUFF];

    const int lane = threadIdx.x;
    const int h = lane >> 4, jj = lane & 15;
    int mat = blockIdx.x * 2 + h;
    const bool alive = (mat < B);
    if (!alive) mat = B - 1;
    const int c0 = jj, c1 = jj + 16;

    float* myA = smem + h * MOFF;          // Xs -> P (squaring chain)
    float* myB = myA + BUFF;               // X2s
    float* myD = myA + 2 * BUFF;           // B2 -> (M1+B1)
    const uint32_t aA = (uint32_t)__cvta_generic_to_shared(myA);
    const uint32_t aD = aA + (uint32_t)(2 * BUFF * 4);

    // Load X columns c0,c1 into regs; mirror full X into bufA (A-operand, stage 0).
    const float* src = in + (size_t)mat * 1024;
    float b0[32], b1[32];
#pragma unroll
    for (int i = 0; i < 32; ++i) { b0[i] = src[i * 32 + c0]; b1[i] = src[i * 32 + c1]; }
#pragma unroll
    for (int i = 0; i < 32; ++i) {
        myA[i * STRIDE + c0] = b0[i];
        myA[i * STRIDE + c1] = b1[i];
    }
    __syncwarp();

    u64 acc0[16], acc1[16];
    float c0v[32], c1v[32];

    // ---- stage 0: X2 = X * X  (A = X smem, B = X regs)
    mm2(aA, b0, b1, acc0, acc1);
#pragma unroll
    for (int p = 0; p < 16; ++p) {
        upk2(c0v[2 * p], c0v[2 * p + 1], acc0[p]);
        upk2(c1v[2 * p], c1v[2 * p + 1], acc1[p]);
    }
    __syncwarp();

    // Spectral bound per matrix: ||X||_2 <= sqrt(min(||X2||_1, ||X2||_F)).
    float sa = 0.f, sb = 0.f, fb = 0.f;
#pragma unroll
    for (int i = 0; i < 32; ++i) {
        sa += fabsf(c0v[i]); sb += fabsf(c1v[i]);
        fb += c0v[i] * c0v[i] + c1v[i] * c1v[i];
    }
    float rs = fmaxf(sa, sb);
#pragma unroll
    for (int off = 8; off > 0; off >>= 1) {   // reduce within half-warp (one matrix)
        rs = fmaxf(rs, __shfl_xor_sync(0xffffffffu, rs, off));
        fb += __shfl_xor_sync(0xffffffffu, fb, off);
    }
    float bnd = sqrtf(fminf(rs, sqrtf(fb)));
    bnd = fmaxf(bnd, __shfl_xor_sync(0xffffffffu, bnd, 16));  // uniform k across warp
    int e = 0; (void)frexpf(bnd, &e);        // bnd <= 2^e
    const int kk = e < 0 ? 0 : (e > 24 ? 24 : e);
    const int total = 4 + kk;
    const float s1 = exp2f(-(float)kk), s2 = s1 * s1;

    // Store Xs -> bufA, X2s -> bufB; bcol := X2s.
#pragma unroll
    for (int i = 0; i < 32; ++i) {
        myA[i * STRIDE + c0] = b0[i] * s1;
        myA[i * STRIDE + c1] = b1[i] * s1;
        float x20 = c0v[i] * s2, x21 = c1v[i] * s2;
        myB[i * STRIDE + c0] = x20;
        myB[i * STRIDE + c1] = x21;
        b0[i] = x20; b1[i] = x21;
    }
    __syncwarp();

    // ---- stage 1: Z = Xs * X2s  (A = Xs smem, B = X2s regs) -> Z stays in regs
    mm2(aA, b0, b1, acc0, acc1);
#pragma unroll
    for (int p = 0; p < 16; ++p) {           // unpack straight into bcol (Z)
        upk2(b0[2 * p], b0[2 * p + 1], acc0[p]);
        upk2(b1[2 * p], b1[2 * p + 1], acc1[p]);
    }
    __syncwarp();
    // Build B2 = I/720 + Xs/5040 + X2s/40320 -> bufD.
#pragma unroll
    for (int i = 0; i < 32; ++i) {
        float xs0 = myA[i * STRIDE + c0], xs1 = myA[i * STRIDE + c1];
        float x20 = myB[i * STRIDE + c0], x21 = myB[i * STRIDE + c1];
        float d0 = (i == c0 ? (1.f / 720.f) : 0.f) + xs0 * (1.f / 5040.f) + x20 * (1.f / 40320.f);
        float d1 = (i == c1 ? (1.f / 720.f) : 0.f) + xs1 * (1.f / 5040.f) + x21 * (1.f / 40320.f);
        myD[i * STRIDE + c0] = d0;
        myD[i * STRIDE + c1] = d1;
    }
    __syncwarp();

    // ---- stage 2: M1 = B2 * Z  (A = D smem, B = Z regs)
    mm2(aD, b0, b1, acc0, acc1);
#pragma unroll
    for (int p = 0; p < 16; ++p) {
        upk2(c0v[2 * p], c0v[2 * p + 1], acc0[p]);
        upk2(c1v[2 * p], c1v[2 * p + 1], acc1[p]);
    }
    __syncwarp();
    // D := M1 + B1, B1 = I/6 + Xs/24 + X2s/120.
#pragma unroll
    for (int i = 0; i < 32; ++i) {
        float xs0 = myA[i * STRIDE + c0], xs1 = myA[i * STRIDE + c1];
        float x20 = myB[i * STRIDE + c0], x21 = myB[i * STRIDE + c1];
        float v0 = c0v[i] + (i == c0 ? (1.f / 6.f) : 0.f) + xs0 * (1.f / 24.f) + x20 * (1.f / 120.f);
        float v1 = c1v[i] + (i == c1 ? (1.f / 6.f) : 0.f) + xs1 * (1.f / 24.f) + x21 * (1.f / 120.f);
        myD[i * STRIDE + c0] = v0;
        myD[i * STRIDE + c1] = v1;
    }
    __syncwarp();

    // ---- stage 3: M2 = (M1+B1) * Z ; P = M2 + I + Xs + X2s/2
    mm2(aD, b0, b1, acc0, acc1);
#pragma unroll
    for (int p = 0; p < 16; ++p) {           // result into bcol, then add B0 terms
        upk2(b0[2 * p], b0[2 * p + 1], acc0[p]);
        upk2(b1[2 * p], b1[2 * p + 1], acc1[p]);
    }
    __syncwarp();
#pragma unroll
    for (int i = 0; i < 32; ++i) {
        float xs0 = myA[i * STRIDE + c0], xs1 = myA[i * STRIDE + c1];
        float x20 = myB[i * STRIDE + c0], x21 = myB[i * STRIDE + c1];
        b0[i] += (i == c0 ? 1.f : 0.f) + xs0 + x20 * 0.5f;
        b1[i] += (i == c1 ? 1.f : 0.f) + xs1 + x21 * 0.5f;
    }
    __syncwarp();   // all Xs/X2s reads done before P overwrites bufA
    if (total > 4) {
#pragma unroll
        for (int i = 0; i < 32; ++i) {
            myA[i * STRIDE + c0] = b0[i];
            myA[i * STRIDE + c1] = b1[i];
        }
    }
    __syncwarp();

    // ---- squarings: P = P * P  (A = P smem, B = P regs)
    for (int s = 4; s < total; ++s) {
        mm2(aA, b0, b1, acc0, acc1);
#pragma unroll
        for (int p = 0; p < 16; ++p) {
            upk2(b0[2 * p], b0[2 * p + 1], acc0[p]);
            upk2(b1[2 * p], b1[2 * p + 1], acc1[p]);
        }
        __syncwarp();
        if (s < total - 1) {                 // last squaring: result goes to gmem only
#pragma unroll
            for (int i = 0; i < 32; ++i) {
                myA[i * STRIDE + c0] = b0[i];
                myA[i * STRIDE + c1] = b1[i];
            }
        }
        __syncwarp();
    }

    if (alive) {
        float* dst = out + (size_t)mat * 1024;
#pragma unroll
        for (int i = 0; i < 32; ++i) {
            dst[i * 32 + c0] = b0[i];
            dst[i * 32 + c1] = b1[i];
        }
    }
}

extern "C" void kernel_launch(void* const* d_in, const int* in_sizes, int n_in,
                              void* d_out, int out_size) {
    (void)n_in; (void)out_size;
    const float* x = (const float*)d_in[0];
    float* out = (float*)d_out;
    const int B = in_sizes[0] / 1024;
    const int ctas = (B + 1) / 2;
    ExpEig_52553219834314_kernel<<<ctas, 32>>>(x, out, B);
}